// round 4
// baseline (speedup 1.0000x reference)
#include <cuda_runtime.h>

// Retina glimpse: x [B=16384, C=3, 32, 32] f32, l [B,2] f32 in [-1,1].
// Outputs concatenated into d_out:
//   full  [B,3,32,32] : x masked to the valid part of the 16x16 window, else 0
//   patch [B,3,16,16] : gathered window, 0 where out of [0,32) bounds

#define BB 16384
#define CC 3
#define HH 32
#define GG 16
#define FULL_PER_B (CC*HH*HH)   // 3072 floats
#define PATCH_PER_B (CC*GG*GG)  // 768 floats
#define SPB 16                  // samples per CTA
#define NBLK (BB / SPB)         // 1024 CTAs -> ~1 wave on 148 SMs at occ 8

__global__ __launch_bounds__(256) void retina_kernel(
    const float* __restrict__ x,
    const float* __restrict__ l,
    float* __restrict__ full,
    float* __restrict__ patch)
{
    const int b0 = blockIdx.x * SPB;
    const int tid = threadIdx.x;

    // Prime the l cache line(s) for this CTA's 16 samples (32 floats = 128B).
    float lpr = __ldg(&l[2 * b0]);
    (void)lpr;

    #pragma unroll 2
    for (int s = 0; s < SPB; ++s) {
        const int b = b0 + s;

        // L1-hit broadcast loads (line primed above).
        float l0 = fminf(fmaxf(__ldg(&l[2 * b + 0]), -1.0f), 1.0f);
        float l1 = fminf(fmaxf(__ldg(&l[2 * b + 1]), -1.0f), 1.0f);
        const int rs = (int)(0.5f * ((l0 + 1.0f) * 32.0f)) - GG / 2;
        const int cs = (int)(0.5f * ((l1 + 1.0f) * 32.0f)) - GG / 2;

        const float* xb = x + (size_t)b * FULL_PER_B;
        float* fb = full + (size_t)b * FULL_PER_B;

        // ---- full phase: 768 float4/sample, 3 per thread; batch loads ----
        float4 xv[3];
        int  w0a[3];
        bool ld[3];
        #pragma unroll
        for (int it = 0; it < 3; ++it) {
            int v = it * 256 + tid;         // [0,768)
            int ch  = v >> 8;
            int rem = v & 255;
            int h   = rem >> 3;
            int w0  = (rem & 7) << 2;
            w0a[it] = w0;
            bool rowin = (h >= rs) && (h < rs + GG);
            ld[it] = rowin && (w0 + 3 >= cs) && (w0 <= cs + GG - 1);
            xv[it] = make_float4(0.f, 0.f, 0.f, 0.f);
            if (ld[it])
                xv[it] = *(const float4*)(xb + (ch << 10) + (h << 5) + w0);
        }
        #pragma unroll
        for (int it = 0; it < 3; ++it) {
            int v = it * 256 + tid;
            int w0 = w0a[it];
            float4 out;
            out.x = (ld[it] && w0 + 0 >= cs && w0 + 0 < cs + GG) ? xv[it].x : 0.f;
            out.y = (ld[it] && w0 + 1 >= cs && w0 + 1 < cs + GG) ? xv[it].y : 0.f;
            out.z = (ld[it] && w0 + 2 >= cs && w0 + 2 < cs + GG) ? xv[it].z : 0.f;
            out.w = (ld[it] && w0 + 3 >= cs && w0 + 3 < cs + GG) ? xv[it].w : 0.f;
            __stcs((float4*)(fb + ((size_t)v << 2)), out);   // never re-read
        }

        // ---- patch phase: 192 float4/sample, threads 0..191 (L1 re-hits) ----
        if (tid < 192) {
            float* pb = patch + (size_t)b * PATCH_PER_B;
            int e4  = tid;                  // float4 index [0,192)
            int ch  = e4 >> 6;
            int rem = e4 & 63;
            int i   = rem >> 2;             // patch row
            int j0  = (rem & 3) << 2;       // first patch col of this float4
            int row = rs + i;
            float4 out = make_float4(0.f, 0.f, 0.f, 0.f);
            if (row >= 0 && row < 32) {
                const float* xr = xb + (ch << 10) + (row << 5);
                int c0 = cs + j0;
                if (c0 + 0 >= 0 && c0 + 0 < 32) out.x = xr[c0 + 0];
                if (c0 + 1 >= 0 && c0 + 1 < 32) out.y = xr[c0 + 1];
                if (c0 + 2 >= 0 && c0 + 2 < 32) out.z = xr[c0 + 2];
                if (c0 + 3 >= 0 && c0 + 3 < 32) out.w = xr[c0 + 3];
            }
            __stcs((float4*)(pb + ((size_t)e4 << 2)), out);
        }
    }
}

extern "C" void kernel_launch(void* const* d_in, const int* in_sizes, int n_in,
                              void* d_out, int out_size)
{
    const float* x = (const float*)d_in[0];   // [16384,3,32,32]
    const float* l = (const float*)d_in[1];   // [16384,2]
    float* full  = (float*)d_out;
    float* patch = (float*)d_out + (size_t)BB * FULL_PER_B;
    retina_kernel<<<NBLK, 256>>>(x, l, full, patch);
}

// round 5
// speedup vs baseline: 1.1683x; 1.1683x over previous
#include <cuda_runtime.h>

// Retina glimpse: x [B=16384, C=3, 32, 32] f32, l [B,2] f32 in [-1,1].
// Outputs concatenated into d_out:
//   full  [B,3,32,32] : x masked to the valid part of the 16x16 window, else 0
//   patch [B,3,16,16] : gathered window, 0 where out of [0,32) bounds
//
// Strategy: stage the window in smem (dense LDG burst), then a pure STG burst.

#define BB 16384
#define CC 3
#define HH 32
#define GG 16
#define FULL_PER_B (CC*HH*HH)   // 3072 floats
#define PATCH_PER_B (CC*GG*GG)  // 768 floats

__global__ __launch_bounds__(256) void retina_kernel(
    const float* __restrict__ x,
    const float* __restrict__ l,
    float* __restrict__ full,
    float* __restrict__ patch)
{
    const int b = blockIdx.x;
    const int tid = threadIdx.x;

    // Window corner (every thread; l loads are same-line L1 broadcasts).
    float l0 = fminf(fmaxf(__ldg(&l[2 * b + 0]), -1.0f), 1.0f);
    float l1 = fminf(fmaxf(__ldg(&l[2 * b + 1]), -1.0f), 1.0f);
    const int rs = (int)(0.5f * ((l0 + 1.0f) * 32.0f)) - GG / 2;  // [-8,24]
    const int cs = (int)(0.5f * ((l1 + 1.0f) * 32.0f)) - GG / 2;  // [-8,24]

    // Aligned column span covering the in-bounds part of the window.
    const int c_lo = max(cs, 0);
    const int c_hi = min(cs + GG, HH);      // > c_lo always
    const int q0 = c_lo >> 2;               // first aligned quad
    const int q1 = (c_hi - 1) >> 2;         // last aligned quad  (q1-q0 <= 4)

    const float* xb = x + (size_t)b * FULL_PER_B;

    // smem window: [ch][row-in-window][quad], quads q0..q0+5
    __shared__ float4 sm[CC][GG][6];

    // ---- Phase 1: dense load burst (288 tasks, 1-2 LDG.128 per thread) ----
    #pragma unroll
    for (int t = tid; t < CC * GG * 6; t += 256) {
        int ch   = t / (GG * 6);
        int rem  = t % (GG * 6);
        int rloc = rem / 6;
        int qi   = rem % 6;
        int r = rs + rloc;
        int q = q0 + qi;
        float4 v = make_float4(0.f, 0.f, 0.f, 0.f);
        if (r >= 0 && r < HH && q <= q1)
            v = *(const float4*)(xb + (ch << 10) + (r << 5) + (q << 2));
        sm[ch][rloc][qi] = v;
    }
    __syncthreads();

    // ---- Phase 2a: full store burst (768 float4/sample, 3 per thread) ----
    float* fb = full + (size_t)b * FULL_PER_B;
    #pragma unroll
    for (int it = 0; it < 3; ++it) {
        int v = it * 256 + tid;             // [0,768)
        int ch  = v >> 8;
        int rem = v & 255;
        int h   = rem >> 3;
        int w0  = (rem & 7) << 2;
        float4 out = make_float4(0.f, 0.f, 0.f, 0.f);
        bool overlap = (h >= rs) && (h < rs + GG) &&
                       (w0 + 3 >= cs) && (w0 <= cs + GG - 1);
        if (overlap) {
            float4 xv = sm[ch][h - rs][(w0 >> 2) - q0];
            out.x = (w0 + 0 >= cs && w0 + 0 < cs + GG) ? xv.x : 0.f;
            out.y = (w0 + 1 >= cs && w0 + 1 < cs + GG) ? xv.y : 0.f;
            out.z = (w0 + 2 >= cs && w0 + 2 < cs + GG) ? xv.z : 0.f;
            out.w = (w0 + 3 >= cs && w0 + 3 < cs + GG) ? xv.w : 0.f;
        }
        __stcs((float4*)(fb + ((size_t)v << 2)), out);  // never re-read
    }

    // ---- Phase 2b: patch store burst (192 float4/sample, threads 0..191) ----
    if (tid < 192) {
        float* pb = patch + (size_t)b * PATCH_PER_B;
        int e4  = tid;                      // float4 index [0,192)
        int ch  = e4 >> 6;
        int rem = e4 & 63;
        int i   = rem >> 2;                 // patch row [0,16)
        int j0  = (rem & 3) << 2;           // first patch col of this float4
        int row = rs + i;
        float4 out = make_float4(0.f, 0.f, 0.f, 0.f);
        if (row >= 0 && row < HH) {
            const float* smf = (const float*)&sm[ch][i][0];
            int base = q0 << 2;             // first column held in smem row
            int c0 = cs + j0;
            if (c0 + 0 >= 0 && c0 + 0 < HH) out.x = smf[c0 + 0 - base];
            if (c0 + 1 >= 0 && c0 + 1 < HH) out.y = smf[c0 + 1 - base];
            if (c0 + 2 >= 0 && c0 + 2 < HH) out.z = smf[c0 + 2 - base];
            if (c0 + 3 >= 0 && c0 + 3 < HH) out.w = smf[c0 + 3 - base];
        }
        __stcs((float4*)(pb + ((size_t)e4 << 2)), out);
    }
}

extern "C" void kernel_launch(void* const* d_in, const int* in_sizes, int n_in,
                              void* d_out, int out_size)
{
    const float* x = (const float*)d_in[0];   // [16384,3,32,32]
    const float* l = (const float*)d_in[1];   // [16384,2]
    float* full  = (float*)d_out;
    float* patch = (float*)d_out + (size_t)BB * FULL_PER_B;
    retina_kernel<<<BB, 256>>>(x, l, full, patch);
}

// round 6
// speedup vs baseline: 1.2231x; 1.0469x over previous
#include <cuda_runtime.h>

// Retina glimpse: x [B=16384, C=3, 32, 32] f32, l [B,2] f32 in [-1,1].
// Outputs concatenated into d_out:
//   full  [B,3,32,32] : x masked to the valid part of the 16x16 window, else 0
//   patch [B,3,16,16] : gathered window, 0 where out of [0,32) bounds
//
// Key idea this round: zero stores (most of `full`) must NOT carry a
// scoreboard wait on the window loads. Loads, independent zero-stores, and
// dependent window-stores are three separate statically-ordered groups.

#define BB 16384
#define CC 3
#define HH 32
#define GG 16
#define FULL_PER_B (CC*HH*HH)   // 3072 floats
#define PATCH_PER_B (CC*GG*GG)  // 768 floats

__global__ __launch_bounds__(256) void retina_kernel(
    const float* __restrict__ x,
    const float* __restrict__ l,
    float* __restrict__ full,
    float* __restrict__ patch)
{
    const int b = blockIdx.x;
    const int tid = threadIdx.x;

    // Window corner (per-thread; l loads are same-line L1 broadcasts).
    float l0 = fminf(fmaxf(__ldg(&l[2 * b + 0]), -1.0f), 1.0f);
    float l1 = fminf(fmaxf(__ldg(&l[2 * b + 1]), -1.0f), 1.0f);
    const int rs = (int)(0.5f * ((l0 + 1.0f) * 32.0f)) - GG / 2;  // [-8,24]
    const int cs = (int)(0.5f * ((l1 + 1.0f) * 32.0f)) - GG / 2;  // [-8,24]

    const float* xb = x + (size_t)b * FULL_PER_B;
    float* fb = full + (size_t)b * FULL_PER_B;
    const float4 z4 = make_float4(0.f, 0.f, 0.f, 0.f);

    // Per-thread quad geometry for the 3 full-phase tasks.
    int  w0a[3], ha[3], cha[3];
    bool ov[3];
    #pragma unroll
    for (int it = 0; it < 3; ++it) {
        int v = it * 256 + tid;             // [0,768) float4 index
        cha[it] = v >> 8;
        int rem = v & 255;
        ha[it]  = rem >> 3;
        w0a[it] = (rem & 7) << 2;
        ov[it] = (ha[it] >= rs) && (ha[it] < rs + GG) &&
                 (w0a[it] + 3 >= cs) && (w0a[it] <= cs + GG - 1);
    }

    // ---- Group 1: issue window loads (only real DRAM reads) ----
    float4 xv[3];
    #pragma unroll
    for (int it = 0; it < 3; ++it) {
        xv[it] = z4;
        if (ov[it])
            xv[it] = *(const float4*)(xb + (cha[it] << 10) + (ha[it] << 5) + w0a[it]);
    }

    // ---- Group 2: independent zero stores (no scoreboard wait) ----
    // These are ~73% of full-phase stores and keep DRAM write-busy while
    // Group 1 loads are in flight.
    #pragma unroll
    for (int it = 0; it < 3; ++it) {
        int v = it * 256 + tid;
        if (!ov[it])
            __stcs((float4*)(fb + ((size_t)v << 2)), z4);
    }

    // ---- Group 3: dependent window stores ----
    #pragma unroll
    for (int it = 0; it < 3; ++it) {
        if (ov[it]) {
            int v = it * 256 + tid;
            int w0 = w0a[it];
            float4 out;
            out.x = (w0 + 0 >= cs && w0 + 0 < cs + GG) ? xv[it].x : 0.f;
            out.y = (w0 + 1 >= cs && w0 + 1 < cs + GG) ? xv[it].y : 0.f;
            out.z = (w0 + 2 >= cs && w0 + 2 < cs + GG) ? xv[it].z : 0.f;
            out.w = (w0 + 3 >= cs && w0 + 3 < cs + GG) ? xv[it].w : 0.f;
            __stcs((float4*)(fb + ((size_t)v << 2)), out);
        }
    }

    // ---- Patch phase: 192 float4/sample, threads 0..191 (L1 re-hits) ----
    if (tid < 192) {
        float* pb = patch + (size_t)b * PATCH_PER_B;
        int e4  = tid;                      // float4 index [0,192)
        int ch  = e4 >> 6;
        int rem = e4 & 63;
        int i   = rem >> 2;                 // patch row [0,16)
        int j0  = (rem & 3) << 2;           // first patch col of this float4
        int row = rs + i;
        float4 out = z4;
        if (row >= 0 && row < HH) {
            const float* xr = xb + (ch << 10) + (row << 5);
            int c0 = cs + j0;
            if (c0 + 0 >= 0 && c0 + 0 < HH) out.x = xr[c0 + 0];
            if (c0 + 1 >= 0 && c0 + 1 < HH) out.y = xr[c0 + 1];
            if (c0 + 2 >= 0 && c0 + 2 < HH) out.z = xr[c0 + 2];
            if (c0 + 3 >= 0 && c0 + 3 < HH) out.w = xr[c0 + 3];
        }
        __stcs((float4*)(pb + ((size_t)e4 << 2)), out);
    }
}

extern "C" void kernel_launch(void* const* d_in, const int* in_sizes, int n_in,
                              void* d_out, int out_size)
{
    const float* x = (const float*)d_in[0];   // [16384,3,32,32]
    const float* l = (const float*)d_in[1];   // [16384,2]
    float* full  = (float*)d_out;
    float* patch = (float*)d_out + (size_t)BB * FULL_PER_B;
    retina_kernel<<<BB, 256>>>(x, l, full, patch);
}